// round 7
// baseline (speedup 1.0000x reference)
#include <cuda_runtime.h>
#include <cuda_fp16.h>
#include <cstddef>
#include <cstdint>

#define Bn 8192
#define Dn 512
#define Hn 1024
#define KV 11
#define NV 12
#define NPAIR 78
#define EPSF 1e-8f

// ---------------------------------------------------------------------------
// Scratch: fp16 activations [rows, K]; weights transposed fp16 WT[n, K];
// encodings Z in fp16.
// ---------------------------------------------------------------------------
__device__ __align__(1024) __half g_T[(size_t)NV * Bn * Dn];
__device__ __align__(1024) __half g_H[(size_t)NV * Bn * Hn];
__device__ __align__(1024) __half g_Z[(size_t)NV * Bn * Hn];
__device__ __align__(1024) __half g_WT1[(size_t)KV * Hn * Dn];
__device__ __align__(1024) __half g_WT2[(size_t)KV * Dn * Hn];
__device__ __align__(1024) __half g_WE1[(size_t)Hn * Dn];
__device__ __align__(1024) __half g_WE2[(size_t)Hn * Hn];

// ---------------------------------------------------------------------------
__device__ __forceinline__ uint32_t smem_u32(const void* p) {
    uint32_t a;
    asm("{ .reg .u64 t; cvta.to.shared.u64 t, %1; cvt.u32.u64 %0, t; }" : "=r"(a) : "l"(p));
    return a;
}
__device__ __forceinline__ void cpa16(uint32_t dst, const void* src) {
    asm volatile("cp.async.cg.shared.global [%0], [%1], 16;" :: "r"(dst), "l"(src) : "memory");
}
#define CP_COMMIT() asm volatile("cp.async.commit_group;" ::: "memory")
#define CP_WAIT2()  asm volatile("cp.async.wait_group 2;" ::: "memory")

__device__ __forceinline__ void ldm4(uint32_t* r, uint32_t addr) {
    asm volatile("ldmatrix.sync.aligned.m8n8.x4.shared.b16 {%0,%1,%2,%3}, [%4];"
                 : "=r"(r[0]), "=r"(r[1]), "=r"(r[2]), "=r"(r[3]) : "r"(addr));
}
__device__ __forceinline__ void mma16816(float* d, const uint32_t* a, const uint32_t* b) {
    asm volatile(
        "mma.sync.aligned.m16n8k16.row.col.f32.f16.f16.f32 "
        "{%0,%1,%2,%3}, {%4,%5,%6,%7}, {%8,%9}, {%0,%1,%2,%3};"
        : "+f"(d[0]), "+f"(d[1]), "+f"(d[2]), "+f"(d[3])
        : "r"(a[0]), "r"(a[1]), "r"(a[2]), "r"(a[3]), "r"(b[0]), "r"(b[1]));
}
__device__ __forceinline__ float tanh_fast(float x) {
    float y;
    asm("tanh.approx.f32 %0, %1;" : "=f"(y) : "f"(x));
    return y;
}

// ---------------------------------------------------------------------------
// fp16 GEMM (fp32 accum):  C = act(A @ Bw^T + bias),  A=[M,K], Bw=[N,K]
// CTA 128x256, K-chunk 64, 4 stages (48KB/stage), 512 threads.
// ---------------------------------------------------------------------------
#define TILE_M 128
#define TILE_N 256
#define BK 64
#define STAGES 4
#define A_BYTES (TILE_M * 128)
#define STAGE_BYTES (A_BYTES + TILE_N * 128)
#define GEMM_SMEM (STAGES * STAGE_BYTES)

template <int ACT>
__global__ void __launch_bounds__(512, 1) gemm_mma(
    const __half* __restrict__ A, const __half* __restrict__ Bw,
    const float* __restrict__ bias, __half* __restrict__ Cout,
    int N, int Kd, size_t sA, size_t sB, size_t sBias, size_t sC)
{
    extern __shared__ __align__(1024) char smem[];
    const uint32_t sb = smem_u32(smem);
    const int tid = threadIdx.x, wid = tid >> 5, lane = tid & 31;
    const int bz = blockIdx.z;
    A    += (size_t)bz * sA;
    Bw   += (size_t)bz * sB;
    bias += (size_t)bz * sBias;

    const int bm = blockIdx.y * TILE_M;
    const int bn = blockIdx.x * TILE_N;
    const int total = Kd / BK;

    // ---- producer mapping ----
    const int prow = tid >> 3;
    const int pch  = tid & 7;
    const uint32_t doff = (uint32_t)(prow * 128) +
                          (((uint32_t)(pch * 16)) ^ (uint32_t)((prow & 7) << 4));
    const __half* Ag = A  + (size_t)(bm + prow) * Kd + pch * 8;
    const __half* Bg = Bw + (size_t)(bn + prow) * Kd + pch * 8;

    // ---- warp compute mapping: 4 m-warps x 4 n-warps (32x64 each) ----
    const int m_off = (wid & 3) * 32;
    const int n_off = (wid >> 2) * 64;
    const int ar = lane & 15, ah = lane >> 4;
    const uint32_t aXor = (uint32_t)((ar & 7) << 4);
    uint32_t aRow[2];
#pragma unroll
    for (int mi = 0; mi < 2; mi++)
        aRow[mi] = (uint32_t)((m_off + mi * 16 + ar) * 128);
    const uint32_t aKad = (uint32_t)(ah * 16);
    const int l8 = lane & 7, sel = lane >> 3;
    const uint32_t bXor = (uint32_t)((l8 & 7) << 4);
    uint32_t bRow[4];
#pragma unroll
    for (int j = 0; j < 4; j++)
        bRow[j] = (uint32_t)((n_off + j * 16 + ((sel >> 1) * 8) + l8) * 128);
    const uint32_t bKad = (uint32_t)((sel & 1) * 16);

    float acc[2][8][4];
#pragma unroll
    for (int mi = 0; mi < 2; mi++)
#pragma unroll
        for (int nj = 0; nj < 8; nj++)
#pragma unroll
            for (int c = 0; c < 4; c++) acc[mi][nj][c] = 0.0f;

    auto load_chunk = [&](int c, int s) {
        const int k0 = c * BK;
        const uint32_t ab = sb + s * STAGE_BYTES;
        const uint32_t bb = ab + A_BYTES;
#pragma unroll
        for (int i = 0; i < 2; i++)
            cpa16(ab + doff + (uint32_t)(i * 8192), Ag + (size_t)(64 * i) * Kd + k0);
#pragma unroll
        for (int i = 0; i < 4; i++)
            cpa16(bb + doff + (uint32_t)(i * 8192), Bg + (size_t)(64 * i) * Kd + k0);
    };

    for (int s = 0; s < STAGES - 1; s++) {
        load_chunk(s, s);
        CP_COMMIT();
    }

    for (int it = 0; it < total; it++) {
        CP_WAIT2();
        __syncthreads();
        const int nc = it + STAGES - 1;
        if (nc < total) load_chunk(nc, nc % STAGES);
        CP_COMMIT();

        const int s = it % STAGES;
        const uint32_t ab = sb + s * STAGE_BYTES;
        const uint32_t bb = ab + A_BYTES;
#pragma unroll
        for (int ks = 0; ks < BK / 16; ks++) {
            uint32_t af[2][4];
            uint32_t bfr[8][2];
#pragma unroll
            for (int mi = 0; mi < 2; mi++)
                ldm4(af[mi], ab + aRow[mi] + (((uint32_t)(ks * 32) + aKad) ^ aXor));
#pragma unroll
            for (int j = 0; j < 4; j++) {
                uint32_t r[4];
                ldm4(r, bb + bRow[j] + (((uint32_t)(ks * 32) + bKad) ^ bXor));
                bfr[2 * j][0] = r[0]; bfr[2 * j][1] = r[1];
                bfr[2 * j + 1][0] = r[2]; bfr[2 * j + 1][1] = r[3];
            }
#pragma unroll
            for (int mi = 0; mi < 2; mi++)
#pragma unroll
                for (int nj = 0; nj < 8; nj++)
                    mma16816(acc[mi][nj], af[mi], bfr[nj]);
        }
    }

    // ---- epilogue (always fp16 out) ----
    const int crow = lane >> 2;
    const int ccol = (lane & 3) * 2;
#pragma unroll
    for (int nj = 0; nj < 8; nj++) {
        const int col = bn + n_off + nj * 8 + ccol;
        const float2 bb2 = *(const float2*)(bias + col);
#pragma unroll
        for (int mi = 0; mi < 2; mi++) {
            const int r0 = bm + m_off + mi * 16 + crow;
#pragma unroll
            for (int h = 0; h < 2; h++) {
                const int row = r0 + 8 * h;
                float v0 = acc[mi][nj][2 * h + 0] + bb2.x;
                float v1 = acc[mi][nj][2 * h + 1] + bb2.y;
                if (ACT == 1) { v0 = tanh_fast(v0); v1 = tanh_fast(v1); }
                else if (ACT == 2) { v0 = fmaxf(v0, 0.f); v1 = fmaxf(v1, 0.f); }
                __half2 hh = __halves2half2(__float2half_rn(v0), __float2half_rn(v1));
                __half* base = Cout + (size_t)bz * sC + (size_t)row * N + col;
                *(uint32_t*)base = *(uint32_t*)&hh;
            }
        }
    }
}

// ---------------------------------------------------------------------------
// Prep kernels
// ---------------------------------------------------------------------------
__global__ void xhalf(const float* __restrict__ x, __half* __restrict__ T0) {
    size_t i = (size_t)blockIdx.x * 256 + threadIdx.x;
    T0[i] = __float2half_rn(x[i]);
}

__global__ void wsplit(const float* __restrict__ W, __half* __restrict__ WT,
                       int Kd, int N, size_t sW, size_t sWT) {
    __shared__ float t[32][33];
    const int bz = blockIdx.z;
    W  += (size_t)bz * sW;
    WT += (size_t)bz * sWT;
    const int n0 = blockIdx.x * 32, k0 = blockIdx.y * 32;
    const int tx = threadIdx.x, ty = threadIdx.y;
    for (int i = 0; i < 32; i += 8)
        t[ty + i][tx] = W[(size_t)(k0 + ty + i) * N + n0 + tx];
    __syncthreads();
    for (int i = 0; i < 32; i += 8)
        WT[(size_t)(n0 + ty + i) * Kd + k0 + tx] = __float2half_rn(t[tx][ty + i]);
}

// ---------------------------------------------------------------------------
// Gram + normalize + score (Z fp16)
// ---------------------------------------------------------------------------
__device__ __forceinline__ void pair_of(int p, int& i, int& j) {
    int ii = 0, rem = p;
    while (rem >= NV - ii) { rem -= NV - ii; ii++; }
    i = ii; j = ii + rem;
}
#define CHUNK 256
#define MAXP_PER_WARP 10

__global__ void gram_score(const __half* __restrict__ Z, float* __restrict__ out) {
    __shared__ float chunk[NV][CHUNK];
    __shared__ float sG[NV * NV];
    const int b = blockIdx.x, tid = threadIdx.x;
    const int lane = tid & 31, warp = tid >> 5;

    int pi_i[MAXP_PER_WARP], pi_j[MAXP_PER_WARP];
    float accp[MAXP_PER_WARP];
#pragma unroll
    for (int pi = 0; pi < MAXP_PER_WARP; pi++) {
        int p = warp + pi * 8;
        if (p < NPAIR) pair_of(p, pi_i[pi], pi_j[pi]);
        else { pi_i[pi] = 0; pi_j[pi] = 0; }
        accp[pi] = 0.0f;
    }
    for (int h0 = 0; h0 < Hn; h0 += CHUNK) {
        __syncthreads();
        // load 12 x CHUNK fp16 slab, convert to fp32 in smem
        for (int i = tid; i < NV * (CHUNK / 8); i += 256) {
            int v = i / (CHUNK / 8);
            int h8 = (i % (CHUNK / 8)) * 8;
            uint4 val = *(const uint4*)(Z + (size_t)v * Bn * Hn + (size_t)b * Hn + h0 + h8);
            const __half2* hp = (const __half2*)&val;
#pragma unroll
            for (int q = 0; q < 4; q++) {
                float2 f = __half22float2(hp[q]);
                chunk[v][h8 + 2 * q]     = f.x;
                chunk[v][h8 + 2 * q + 1] = f.y;
            }
        }
        __syncthreads();
#pragma unroll
        for (int pi = 0; pi < MAXP_PER_WARP; pi++) {
            int p = warp + pi * 8;
            if (p < NPAIR) {
                const float* ri = chunk[pi_i[pi]];
                const float* rj = chunk[pi_j[pi]];
                float s = 0.0f;
#pragma unroll
                for (int t = 0; t < CHUNK / 32; t++)
                    s = fmaf(ri[lane + 32 * t], rj[lane + 32 * t], s);
                accp[pi] += s;
            }
        }
    }
#pragma unroll
    for (int pi = 0; pi < MAXP_PER_WARP; pi++) {
        int p = warp + pi * 8;
        if (p < NPAIR) {
            float s = accp[pi];
#pragma unroll
            for (int o = 16; o; o >>= 1) s += __shfl_xor_sync(0xffffffffu, s, o);
            if (lane == 0) {
                sG[pi_i[pi] * NV + pi_j[pi]] = s;
                sG[pi_j[pi] * NV + pi_i[pi]] = s;
            }
        }
    }
    __syncthreads();
    if (tid == 0) {
        float nm[NV];
#pragma unroll
        for (int i = 0; i < NV; i++) nm[i] = fmaxf(sqrtf(sG[i * NV + i]), EPSF);
        float total = 0.0f;
        for (int k = 1; k < NV; k++) {
            float pos = expf(sG[k] / (nm[0] * nm[k]));
            float neg = 0.0f;
            for (int l = 1; l < NV; l++)
                if (l != k) neg += expf(sG[k * NV + l] / (nm[k] * nm[l]));
            total += logf((pos + neg) / pos);
        }
        out[b] = total;
    }
}

// ---------------------------------------------------------------------------
// Launch
// ---------------------------------------------------------------------------
extern "C" void kernel_launch(void* const* d_in, const int* in_sizes, int n_in,
                              void* d_out, int out_size)
{
    const float* x   = (const float*)d_in[0];
    const float* Wt1 = (const float*)d_in[1];
    const float* bt1 = (const float*)d_in[2];
    const float* Wt2 = (const float*)d_in[3];
    const float* bt2 = (const float*)d_in[4];
    const float* We1 = (const float*)d_in[5];
    const float* be1 = (const float*)d_in[6];
    const float* We2 = (const float*)d_in[7];
    const float* be2 = (const float*)d_in[8];
    float* out = (float*)d_out;

    __half *T, *H, *Z, *WT1, *WT2, *WE1, *WE2;
    cudaGetSymbolAddress((void**)&T, g_T);
    cudaGetSymbolAddress((void**)&H, g_H);
    cudaGetSymbolAddress((void**)&Z, g_Z);
    cudaGetSymbolAddress((void**)&WT1, g_WT1);
    cudaGetSymbolAddress((void**)&WT2, g_WT2);
    cudaGetSymbolAddress((void**)&WE1, g_WE1);
    cudaGetSymbolAddress((void**)&WE2, g_WE2);

    xhalf<<<(Bn * Dn) / 256, 256>>>(x, T);
    wsplit<<<dim3(Hn / 32, Dn / 32, KV), dim3(32, 8)>>>(
        Wt1, WT1, Dn, Hn, (size_t)Dn * Hn, (size_t)Hn * Dn);
    wsplit<<<dim3(Dn / 32, Hn / 32, KV), dim3(32, 8)>>>(
        Wt2, WT2, Hn, Dn, (size_t)Hn * Dn, (size_t)Dn * Hn);
    wsplit<<<dim3(Hn / 32, Dn / 32, 1), dim3(32, 8)>>>(We1, WE1, Dn, Hn, 0, 0);
    wsplit<<<dim3(Hn / 32, Hn / 32, 1), dim3(32, 8)>>>(We2, WE2, Hn, Hn, 0, 0);

    cudaFuncSetAttribute(gemm_mma<1>, cudaFuncAttributeMaxDynamicSharedMemorySize, GEMM_SMEM);
    cudaFuncSetAttribute(gemm_mma<0>, cudaFuncAttributeMaxDynamicSharedMemorySize, GEMM_SMEM);
    cudaFuncSetAttribute(gemm_mma<2>, cudaFuncAttributeMaxDynamicSharedMemorySize, GEMM_SMEM);

    // A1: H[k] = tanh(x @ Wt1[k] + bt1[k])
    gemm_mma<1><<<dim3(Hn / TILE_N, Bn / TILE_M, KV), 512, GEMM_SMEM>>>(
        T, WT1, bt1, H, Hn, Dn,
        (size_t)0, (size_t)Hn * Dn, (size_t)Hn, (size_t)Bn * Hn);

    // A2: T[1+k] = H[k] @ Wt2[k] + bt2[k]
    gemm_mma<0><<<dim3(Dn / TILE_N, Bn / TILE_M, KV), 512, GEMM_SMEM>>>(
        H, WT2, bt2, T + (size_t)Bn * Dn, Dn, Hn,
        (size_t)Bn * Hn, (size_t)Dn * Hn, (size_t)Dn, (size_t)Bn * Dn);

    // B1: H[v] = relu(T[v] @ We1 + be1)
    gemm_mma<2><<<dim3(Hn / TILE_N, Bn / TILE_M, NV), 512, GEMM_SMEM>>>(
        T, WE1, be1, H, Hn, Dn,
        (size_t)Bn * Dn, (size_t)0, (size_t)0, (size_t)Bn * Hn);

    // B2: Z[v] = H[v] @ We2 + be2  (fp16 out)
    gemm_mma<0><<<dim3(Hn / TILE_N, Bn / TILE_M, NV), 512, GEMM_SMEM>>>(
        H, WE2, be2, Z, Hn, Hn,
        (size_t)Bn * Hn, (size_t)0, (size_t)0, (size_t)Bn * Hn);

    gram_score<<<Bn, 256>>>(Z, out);
}

// round 8
// speedup vs baseline: 1.5464x; 1.5464x over previous
#include <cuda_runtime.h>
#include <cuda_fp16.h>
#include <cstddef>
#include <cstdint>

#define Bn 8192
#define Dn 512
#define Hn 1024
#define KV 11
#define NV 12
#define NPAIR 78
#define EPSF 1e-8f

// ---------------------------------------------------------------------------
// Scratch: fp16 activations [rows, K]; weights transposed fp16 WT[n, K];
// encodings Z in fp16.
// ---------------------------------------------------------------------------
__device__ __align__(1024) __half g_T[(size_t)NV * Bn * Dn];
__device__ __align__(1024) __half g_H[(size_t)NV * Bn * Hn];
__device__ __align__(1024) __half g_Z[(size_t)NV * Bn * Hn];
__device__ __align__(1024) __half g_WT1[(size_t)KV * Hn * Dn];
__device__ __align__(1024) __half g_WT2[(size_t)KV * Dn * Hn];
__device__ __align__(1024) __half g_WE1[(size_t)Hn * Dn];
__device__ __align__(1024) __half g_WE2[(size_t)Hn * Hn];

// ---------------------------------------------------------------------------
__device__ __forceinline__ uint32_t smem_u32(const void* p) {
    uint32_t a;
    asm("{ .reg .u64 t; cvta.to.shared.u64 t, %1; cvt.u32.u64 %0, t; }" : "=r"(a) : "l"(p));
    return a;
}
__device__ __forceinline__ void cpa16(uint32_t dst, const void* src) {
    asm volatile("cp.async.cg.shared.global [%0], [%1], 16;" :: "r"(dst), "l"(src) : "memory");
}
#define CP_COMMIT() asm volatile("cp.async.commit_group;" ::: "memory")
#define CP_WAIT2()  asm volatile("cp.async.wait_group 2;" ::: "memory")

__device__ __forceinline__ void ldm4(uint32_t* r, uint32_t addr) {
    asm volatile("ldmatrix.sync.aligned.m8n8.x4.shared.b16 {%0,%1,%2,%3}, [%4];"
                 : "=r"(r[0]), "=r"(r[1]), "=r"(r[2]), "=r"(r[3]) : "r"(addr));
}
__device__ __forceinline__ void mma16816(float* d, const uint32_t* a, const uint32_t* b) {
    asm volatile(
        "mma.sync.aligned.m16n8k16.row.col.f32.f16.f16.f32 "
        "{%0,%1,%2,%3}, {%4,%5,%6,%7}, {%8,%9}, {%0,%1,%2,%3};"
        : "+f"(d[0]), "+f"(d[1]), "+f"(d[2]), "+f"(d[3])
        : "r"(a[0]), "r"(a[1]), "r"(a[2]), "r"(a[3]), "r"(b[0]), "r"(b[1]));
}
__device__ __forceinline__ float tanh_fast(float x) {
    float y;
    asm("tanh.approx.f32 %0, %1;" : "=f"(y) : "f"(x));
    return y;
}

// ---------------------------------------------------------------------------
// fp16 GEMM (fp32 accum):  C = act(A @ Bw^T + bias),  A=[M,K], Bw=[N,K]
// CTA 128x256, K-chunk 64, 4 stages (48KB/stage), 512 threads.
// ---------------------------------------------------------------------------
#define TILE_M 128
#define TILE_N 256
#define BK 64
#define STAGES 4
#define A_BYTES (TILE_M * 128)
#define STAGE_BYTES (A_BYTES + TILE_N * 128)
#define GEMM_SMEM (STAGES * STAGE_BYTES)

template <int ACT>
__global__ void __launch_bounds__(512, 1) gemm_mma(
    const __half* __restrict__ A, const __half* __restrict__ Bw,
    const float* __restrict__ bias, __half* __restrict__ Cout,
    int N, int Kd, size_t sA, size_t sB, size_t sBias, size_t sC)
{
    extern __shared__ __align__(1024) char smem[];
    const uint32_t sb = smem_u32(smem);
    const int tid = threadIdx.x, wid = tid >> 5, lane = tid & 31;
    const int bz = blockIdx.z;
    A    += (size_t)bz * sA;
    Bw   += (size_t)bz * sB;
    bias += (size_t)bz * sBias;

    const int bm = blockIdx.y * TILE_M;
    const int bn = blockIdx.x * TILE_N;
    const int total = Kd / BK;

    // ---- producer mapping ----
    const int prow = tid >> 3;
    const int pch  = tid & 7;
    const uint32_t doff = (uint32_t)(prow * 128) +
                          (((uint32_t)(pch * 16)) ^ (uint32_t)((prow & 7) << 4));
    const __half* Ag = A  + (size_t)(bm + prow) * Kd + pch * 8;
    const __half* Bg = Bw + (size_t)(bn + prow) * Kd + pch * 8;

    // ---- warp compute mapping: 4 m-warps x 4 n-warps (32x64 each) ----
    const int m_off = (wid & 3) * 32;
    const int n_off = (wid >> 2) * 64;
    const int ar = lane & 15, ah = lane >> 4;
    const uint32_t aXor = (uint32_t)((ar & 7) << 4);
    uint32_t aRow[2];
#pragma unroll
    for (int mi = 0; mi < 2; mi++)
        aRow[mi] = (uint32_t)((m_off + mi * 16 + ar) * 128);
    const uint32_t aKad = (uint32_t)(ah * 16);
    const int l8 = lane & 7, sel = lane >> 3;
    const uint32_t bXor = (uint32_t)((l8 & 7) << 4);
    uint32_t bRow[4];
#pragma unroll
    for (int j = 0; j < 4; j++)
        bRow[j] = (uint32_t)((n_off + j * 16 + ((sel >> 1) * 8) + l8) * 128);
    const uint32_t bKad = (uint32_t)((sel & 1) * 16);

    float acc[2][8][4];
#pragma unroll
    for (int mi = 0; mi < 2; mi++)
#pragma unroll
        for (int nj = 0; nj < 8; nj++)
#pragma unroll
            for (int c = 0; c < 4; c++) acc[mi][nj][c] = 0.0f;

    auto load_chunk = [&](int c, int s) {
        const int k0 = c * BK;
        const uint32_t ab = sb + s * STAGE_BYTES;
        const uint32_t bb = ab + A_BYTES;
#pragma unroll
        for (int i = 0; i < 2; i++)
            cpa16(ab + doff + (uint32_t)(i * 8192), Ag + (size_t)(64 * i) * Kd + k0);
#pragma unroll
        for (int i = 0; i < 4; i++)
            cpa16(bb + doff + (uint32_t)(i * 8192), Bg + (size_t)(64 * i) * Kd + k0);
    };

    for (int s = 0; s < STAGES - 1; s++) {
        load_chunk(s, s);
        CP_COMMIT();
    }

    for (int it = 0; it < total; it++) {
        CP_WAIT2();
        __syncthreads();
        const int nc = it + STAGES - 1;
        if (nc < total) load_chunk(nc, nc % STAGES);
        CP_COMMIT();

        const int s = it % STAGES;
        const uint32_t ab = sb + s * STAGE_BYTES;
        const uint32_t bb = ab + A_BYTES;
#pragma unroll
        for (int ks = 0; ks < BK / 16; ks++) {
            uint32_t af[2][4];
            uint32_t bfr[8][2];
#pragma unroll
            for (int mi = 0; mi < 2; mi++)
                ldm4(af[mi], ab + aRow[mi] + (((uint32_t)(ks * 32) + aKad) ^ aXor));
#pragma unroll
            for (int j = 0; j < 4; j++) {
                uint32_t r[4];
                ldm4(r, bb + bRow[j] + (((uint32_t)(ks * 32) + bKad) ^ bXor));
                bfr[2 * j][0] = r[0]; bfr[2 * j][1] = r[1];
                bfr[2 * j + 1][0] = r[2]; bfr[2 * j + 1][1] = r[3];
            }
#pragma unroll
            for (int mi = 0; mi < 2; mi++)
#pragma unroll
                for (int nj = 0; nj < 8; nj++)
                    mma16816(acc[mi][nj], af[mi], bfr[nj]);
        }
    }

    // ---- epilogue (fp16 out) ----
    const int crow = lane >> 2;
    const int ccol = (lane & 3) * 2;
#pragma unroll
    for (int nj = 0; nj < 8; nj++) {
        const int col = bn + n_off + nj * 8 + ccol;
        const float2 bb2 = *(const float2*)(bias + col);
#pragma unroll
        for (int mi = 0; mi < 2; mi++) {
            const int r0 = bm + m_off + mi * 16 + crow;
#pragma unroll
            for (int h = 0; h < 2; h++) {
                const int row = r0 + 8 * h;
                float v0 = acc[mi][nj][2 * h + 0] + bb2.x;
                float v1 = acc[mi][nj][2 * h + 1] + bb2.y;
                if (ACT == 1) { v0 = tanh_fast(v0); v1 = tanh_fast(v1); }
                else if (ACT == 2) { v0 = fmaxf(v0, 0.f); v1 = fmaxf(v1, 0.f); }
                __half2 hh = __halves2half2(__float2half_rn(v0), __float2half_rn(v1));
                __half* base = Cout + (size_t)bz * sC + (size_t)row * N + col;
                *(uint32_t*)base = *(uint32_t*)&hh;
            }
        }
    }
}

// ---------------------------------------------------------------------------
// Prep kernels
// ---------------------------------------------------------------------------
__global__ void xhalf(const float* __restrict__ x, __half* __restrict__ T0) {
    size_t i = (size_t)blockIdx.x * 256 + threadIdx.x;
    float4 v = *(const float4*)(x + 4 * i);
    __half2 a = __floats2half2_rn(v.x, v.y);
    __half2 b = __floats2half2_rn(v.z, v.w);
    uint2 o; o.x = *(uint32_t*)&a; o.y = *(uint32_t*)&b;
    *(uint2*)(T0 + 4 * i) = o;
}

__global__ void wsplit(const float* __restrict__ W, __half* __restrict__ WT,
                       int Kd, int N, size_t sW, size_t sWT) {
    __shared__ float t[32][33];
    const int bz = blockIdx.z;
    W  += (size_t)bz * sW;
    WT += (size_t)bz * sWT;
    const int n0 = blockIdx.x * 32, k0 = blockIdx.y * 32;
    const int tx = threadIdx.x, ty = threadIdx.y;
    for (int i = 0; i < 32; i += 8)
        t[ty + i][tx] = W[(size_t)(k0 + ty + i) * N + n0 + tx];
    __syncthreads();
    for (int i = 0; i < 32; i += 8)
        WT[(size_t)(n0 + ty + i) * Kd + k0 + tx] = __float2half_rn(t[tx][ty + i]);
}

// ---------------------------------------------------------------------------
// Gram + normalize + score (Z fp16)
// ---------------------------------------------------------------------------
__device__ __forceinline__ void pair_of(int p, int& i, int& j) {
    int ii = 0, rem = p;
    while (rem >= NV - ii) { rem -= NV - ii; ii++; }
    i = ii; j = ii + rem;
}
#define CHUNK 256
#define MAXP_PER_WARP 10

__global__ void gram_score(const __half* __restrict__ Z, float* __restrict__ out) {
    __shared__ float chunk[NV][CHUNK];
    __shared__ float sG[NV * NV];
    const int b = blockIdx.x, tid = threadIdx.x;
    const int lane = tid & 31, warp = tid >> 5;

    int pi_i[MAXP_PER_WARP], pi_j[MAXP_PER_WARP];
    float accp[MAXP_PER_WARP];
#pragma unroll
    for (int pi = 0; pi < MAXP_PER_WARP; pi++) {
        int p = warp + pi * 8;
        if (p < NPAIR) pair_of(p, pi_i[pi], pi_j[pi]);
        else { pi_i[pi] = 0; pi_j[pi] = 0; }
        accp[pi] = 0.0f;
    }
    for (int h0 = 0; h0 < Hn; h0 += CHUNK) {
        __syncthreads();
        for (int i = tid; i < NV * (CHUNK / 8); i += 256) {
            int v = i / (CHUNK / 8);
            int h8 = (i % (CHUNK / 8)) * 8;
            uint4 val = *(const uint4*)(Z + (size_t)v * Bn * Hn + (size_t)b * Hn + h0 + h8);
            const __half2* hp = (const __half2*)&val;
#pragma unroll
            for (int q = 0; q < 4; q++) {
                float2 f = __half22float2(hp[q]);
                chunk[v][h8 + 2 * q]     = f.x;
                chunk[v][h8 + 2 * q + 1] = f.y;
            }
        }
        __syncthreads();
#pragma unroll
        for (int pi = 0; pi < MAXP_PER_WARP; pi++) {
            int p = warp + pi * 8;
            if (p < NPAIR) {
                const float* ri = chunk[pi_i[pi]];
                const float* rj = chunk[pi_j[pi]];
                float s = 0.0f;
#pragma unroll
                for (int t = 0; t < CHUNK / 32; t++)
                    s = fmaf(ri[lane + 32 * t], rj[lane + 32 * t], s);
                accp[pi] += s;
            }
        }
    }
#pragma unroll
    for (int pi = 0; pi < MAXP_PER_WARP; pi++) {
        int p = warp + pi * 8;
        if (p < NPAIR) {
            float s = accp[pi];
#pragma unroll
            for (int o = 16; o; o >>= 1) s += __shfl_xor_sync(0xffffffffu, s, o);
            if (lane == 0) {
                sG[pi_i[pi] * NV + pi_j[pi]] = s;
                sG[pi_j[pi] * NV + pi_i[pi]] = s;
            }
        }
    }
    __syncthreads();
    if (tid == 0) {
        float nm[NV];
#pragma unroll
        for (int i = 0; i < NV; i++) nm[i] = fmaxf(sqrtf(sG[i * NV + i]), EPSF);
        float total = 0.0f;
        for (int k = 1; k < NV; k++) {
            float pos = expf(sG[k] / (nm[0] * nm[k]));
            float neg = 0.0f;
            for (int l = 1; l < NV; l++)
                if (l != k) neg += expf(sG[k * NV + l] / (nm[k] * nm[l]));
            total += logf((pos + neg) / pos);
        }
        out[b] = total;
    }
}

// ---------------------------------------------------------------------------
// Launch
// ---------------------------------------------------------------------------
extern "C" void kernel_launch(void* const* d_in, const int* in_sizes, int n_in,
                              void* d_out, int out_size)
{
    const float* x   = (const float*)d_in[0];
    const float* Wt1 = (const float*)d_in[1];
    const float* bt1 = (const float*)d_in[2];
    const float* Wt2 = (const float*)d_in[3];
    const float* bt2 = (const float*)d_in[4];
    const float* We1 = (const float*)d_in[5];
    const float* be1 = (const float*)d_in[6];
    const float* We2 = (const float*)d_in[7];
    const float* be2 = (const float*)d_in[8];
    float* out = (float*)d_out;

    __half *T, *H, *Z, *WT1, *WT2, *WE1, *WE2;
    cudaGetSymbolAddress((void**)&T, g_T);
    cudaGetSymbolAddress((void**)&H, g_H);
    cudaGetSymbolAddress((void**)&Z, g_Z);
    cudaGetSymbolAddress((void**)&WT1, g_WT1);
    cudaGetSymbolAddress((void**)&WT2, g_WT2);
    cudaGetSymbolAddress((void**)&WE1, g_WE1);
    cudaGetSymbolAddress((void**)&WE2, g_WE2);

    xhalf<<<(Bn * Dn) / 1024, 256>>>(x, T);
    wsplit<<<dim3(Hn / 32, Dn / 32, KV), dim3(32, 8)>>>(
        Wt1, WT1, Dn, Hn, (size_t)Dn * Hn, (size_t)Hn * Dn);
    wsplit<<<dim3(Dn / 32, Hn / 32, KV), dim3(32, 8)>>>(
        Wt2, WT2, Hn, Dn, (size_t)Hn * Dn, (size_t)Dn * Hn);
    wsplit<<<dim3(Hn / 32, Dn / 32, 1), dim3(32, 8)>>>(We1, WE1, Dn, Hn, 0, 0);
    wsplit<<<dim3(Hn / 32, Hn / 32, 1), dim3(32, 8)>>>(We2, WE2, Hn, Hn, 0, 0);

    cudaFuncSetAttribute(gemm_mma<1>, cudaFuncAttributeMaxDynamicSharedMemorySize, GEMM_SMEM);
    cudaFuncSetAttribute(gemm_mma<0>, cudaFuncAttributeMaxDynamicSharedMemorySize, GEMM_SMEM);
    cudaFuncSetAttribute(gemm_mma<2>, cudaFuncAttributeMaxDynamicSharedMemorySize, GEMM_SMEM);

    // A1: H[k] = tanh(x @ Wt1[k] + bt1[k])
    gemm_mma<1><<<dim3(Hn / TILE_N, Bn / TILE_M, KV), 512, GEMM_SMEM>>>(
        T, WT1, bt1, H, Hn, Dn,
        (size_t)0, (size_t)Hn * Dn, (size_t)Hn, (size_t)Bn * Hn);

    // A2: T[1+k] = H[k] @ Wt2[k] + bt2[k]
    gemm_mma<0><<<dim3(Dn / TILE_N, Bn / TILE_M, KV), 512, GEMM_SMEM>>>(
        H, WT2, bt2, T + (size_t)Bn * Dn, Dn, Hn,
        (size_t)Bn * Hn, (size_t)Dn * Hn, (size_t)Dn, (size_t)Bn * Dn);

    // B1: H[v] = relu(T[v] @ We1 + be1)
    gemm_mma<2><<<dim3(Hn / TILE_N, Bn / TILE_M, NV), 512, GEMM_SMEM>>>(
        T, WE1, be1, H, Hn, Dn,
        (size_t)Bn * Dn, (size_t)0, (size_t)0, (size_t)Bn * Hn);

    // B2: Z[v] = H[v] @ We2 + be2  (fp16 out)
    gemm_mma<0><<<dim3(Hn / TILE_N, Bn / TILE_M, NV), 512, GEMM_SMEM>>>(
        H, WE2, be2, Z, Hn, Hn,
        (size_t)Bn * Hn, (size_t)0, (size_t)0, (size_t)Bn * Hn);

    gram_score<<<Bn, 256>>>(Z, out);
}

// round 10
// speedup vs baseline: 1.5805x; 1.0220x over previous
#include <cuda_runtime.h>
#include <cuda_fp16.h>
#include <cstddef>
#include <cstdint>

#define Bn 8192
#define Dn 512
#define Hn 1024
#define KV 11
#define NV 12
#define NPAIR 78
#define EPSF 1e-8f

// ---------------------------------------------------------------------------
// Scratch: fp16 activations [rows, K]; weights transposed fp16 WT[n, K];
// encodings Z in fp16.
// ---------------------------------------------------------------------------
__device__ __align__(1024) __half g_T[(size_t)NV * Bn * Dn];
__device__ __align__(1024) __half g_H[(size_t)NV * Bn * Hn];
__device__ __align__(1024) __half g_Z[(size_t)NV * Bn * Hn];
__device__ __align__(1024) __half g_WT1[(size_t)KV * Hn * Dn];
__device__ __align__(1024) __half g_WT2[(size_t)KV * Dn * Hn];
__device__ __align__(1024) __half g_WE1[(size_t)Hn * Dn];
__device__ __align__(1024) __half g_WE2[(size_t)Hn * Hn];

// ---------------------------------------------------------------------------
__device__ __forceinline__ uint32_t smem_u32(const void* p) {
    uint32_t a;
    asm("{ .reg .u64 t; cvta.to.shared.u64 t, %1; cvt.u32.u64 %0, t; }" : "=r"(a) : "l"(p));
    return a;
}
__device__ __forceinline__ void cpa16(uint32_t dst, const void* src) {
    asm volatile("cp.async.cg.shared.global [%0], [%1], 16;" :: "r"(dst), "l"(src) : "memory");
}
#define CP_COMMIT() asm volatile("cp.async.commit_group;" ::: "memory")
#define CP_WAIT2()  asm volatile("cp.async.wait_group 2;" ::: "memory")

__device__ __forceinline__ void ldm4(uint32_t* r, uint32_t addr) {
    asm volatile("ldmatrix.sync.aligned.m8n8.x4.shared.b16 {%0,%1,%2,%3}, [%4];"
                 : "=r"(r[0]), "=r"(r[1]), "=r"(r[2]), "=r"(r[3]) : "r"(addr));
}
// fp16 accumulate: d/c are 2 b32 regs (4 halves)
__device__ __forceinline__ void mma16816_f16(uint32_t* d, const uint32_t* a, const uint32_t* b) {
    asm volatile(
        "mma.sync.aligned.m16n8k16.row.col.f16.f16.f16.f16 "
        "{%0,%1}, {%2,%3,%4,%5}, {%6,%7}, {%0,%1};"
        : "+r"(d[0]), "+r"(d[1])
        : "r"(a[0]), "r"(a[1]), "r"(a[2]), "r"(a[3]), "r"(b[0]), "r"(b[1]));
}
__device__ __forceinline__ float tanh_fast(float x) {
    float y;
    asm("tanh.approx.f32 %0, %1;" : "=f"(y) : "f"(x));
    return y;
}

// ---------------------------------------------------------------------------
// fp16 GEMM (fp16 accum):  C = act(A @ Bw^T + bias),  A=[M,K], Bw=[N,K]
// CTA 128x256, K-chunk 64, 4 stages (48KB/stage), 256 threads.
// 8 warps, 2m x 4n, warp tile 64x64.
// ---------------------------------------------------------------------------
#define TILE_M 128
#define TILE_N 256
#define BK 64
#define STAGES 4
#define A_BYTES (TILE_M * 128)
#define STAGE_BYTES (A_BYTES + TILE_N * 128)
#define GEMM_SMEM (STAGES * STAGE_BYTES)

template <int ACT>
__global__ void __launch_bounds__(256, 1) gemm_mma(
    const __half* __restrict__ A, const __half* __restrict__ Bw,
    const float* __restrict__ bias, __half* __restrict__ Cout,
    int N, int Kd, size_t sA, size_t sB, size_t sBias, size_t sC)
{
    extern __shared__ __align__(1024) char smem[];
    const uint32_t sb = smem_u32(smem);
    const int tid = threadIdx.x, wid = tid >> 5, lane = tid & 31;
    const int bz = blockIdx.z;
    A    += (size_t)bz * sA;
    Bw   += (size_t)bz * sB;
    bias += (size_t)bz * sBias;

    const int bm = blockIdx.y * TILE_M;
    const int bn = blockIdx.x * TILE_N;
    const int total = Kd / BK;

    // ---- producer mapping: 256 threads = 32 rows x 8 granules ----
    const int prow = tid >> 3;            // 0..31
    const int pch  = tid & 7;
    const uint32_t doff = (uint32_t)(prow * 128) +
                          (((uint32_t)(pch * 16)) ^ (uint32_t)((prow & 7) << 4));
    const __half* Ag = A  + (size_t)(bm + prow) * Kd + pch * 8;
    const __half* Bg = Bw + (size_t)(bn + prow) * Kd + pch * 8;

    // ---- warp compute mapping: 2 m-warps x 4 n-warps, warp tile 64x64 ----
    const int m_off = (wid & 1) * 64;
    const int n_off = (wid >> 1) * 64;
    const int ar = lane & 15, ah = lane >> 4;
    const uint32_t aXor = (uint32_t)((ar & 7) << 4);
    uint32_t aRow[4];
#pragma unroll
    for (int mi = 0; mi < 4; mi++)
        aRow[mi] = (uint32_t)((m_off + mi * 16 + ar) * 128);
    const uint32_t aKad = (uint32_t)(ah * 16);
    const int l8 = lane & 7, sel = lane >> 3;
    const uint32_t bXor = (uint32_t)((l8 & 7) << 4);
    uint32_t bRow[4];
#pragma unroll
    for (int j = 0; j < 4; j++)
        bRow[j] = (uint32_t)((n_off + j * 16 + ((sel >> 1) * 8) + l8) * 128);
    const uint32_t bKad = (uint32_t)((sel & 1) * 16);

    uint32_t acc[4][8][2];                // fp16x2 accumulators
#pragma unroll
    for (int mi = 0; mi < 4; mi++)
#pragma unroll
        for (int nj = 0; nj < 8; nj++) {
            acc[mi][nj][0] = 0u;
            acc[mi][nj][1] = 0u;
        }

    auto load_chunk = [&](int c, int s) {
        const int k0 = c * BK;
        const uint32_t ab = sb + s * STAGE_BYTES;
        const uint32_t bb = ab + A_BYTES;
#pragma unroll
        for (int i = 0; i < 4; i++)
            cpa16(ab + doff + (uint32_t)(i * 4096), Ag + (size_t)(32 * i) * Kd + k0);
#pragma unroll
        for (int i = 0; i < 8; i++)
            cpa16(bb + doff + (uint32_t)(i * 4096), Bg + (size_t)(32 * i) * Kd + k0);
    };

    for (int s = 0; s < STAGES - 1; s++) {
        load_chunk(s, s);
        CP_COMMIT();
    }

    for (int it = 0; it < total; it++) {
        CP_WAIT2();
        __syncthreads();
        const int nc = it + STAGES - 1;
        if (nc < total) load_chunk(nc, nc % STAGES);
        CP_COMMIT();

        const int s = it % STAGES;
        const uint32_t ab = sb + s * STAGE_BYTES;
        const uint32_t bb = ab + A_BYTES;
#pragma unroll
        for (int ks = 0; ks < BK / 16; ks++) {
            uint32_t af[4][4];
            uint32_t bfr[8][2];
#pragma unroll
            for (int mi = 0; mi < 4; mi++)
                ldm4(af[mi], ab + aRow[mi] + (((uint32_t)(ks * 32) + aKad) ^ aXor));
#pragma unroll
            for (int j = 0; j < 4; j++) {
                uint32_t r[4];
                ldm4(r, bb + bRow[j] + (((uint32_t)(ks * 32) + bKad) ^ bXor));
                bfr[2 * j][0] = r[0]; bfr[2 * j][1] = r[1];
                bfr[2 * j + 1][0] = r[2]; bfr[2 * j + 1][1] = r[3];
            }
#pragma unroll
            for (int mi = 0; mi < 4; mi++)
#pragma unroll
                for (int nj = 0; nj < 8; nj++)
                    mma16816_f16(acc[mi][nj], af[mi], bfr[nj]);
        }
    }

    // ---- epilogue (fp16 out) ----
    const int crow = lane >> 2;
    const int ccol = (lane & 3) * 2;
#pragma unroll
    for (int nj = 0; nj < 8; nj++) {
        const int col = bn + n_off + nj * 8 + ccol;
        const float2 bb2 = *(const float2*)(bias + col);
#pragma unroll
        for (int mi = 0; mi < 4; mi++) {
            const int r0 = bm + m_off + mi * 16 + crow;
#pragma unroll
            for (int h = 0; h < 2; h++) {
                const int row = r0 + 8 * h;
                float2 f = __half22float2(*(const __half2*)&acc[mi][nj][h]);
                float v0 = f.x + bb2.x;
                float v1 = f.y + bb2.y;
                if (ACT == 1) { v0 = tanh_fast(v0); v1 = tanh_fast(v1); }
                else if (ACT == 2) { v0 = fmaxf(v0, 0.f); v1 = fmaxf(v1, 0.f); }
                __half2 hh = __halves2half2(__float2half_rn(v0), __float2half_rn(v1));
                __half* base = Cout + (size_t)bz * sC + (size_t)row * N + col;
                *(uint32_t*)base = *(uint32_t*)&hh;
            }
        }
    }
}

// ---------------------------------------------------------------------------
// Prep kernels
// ---------------------------------------------------------------------------
__global__ void xhalf(const float* __restrict__ x, __half* __restrict__ T0) {
    size_t i = (size_t)blockIdx.x * 256 + threadIdx.x;
    float4 v = *(const float4*)(x + 4 * i);
    __half2 a = __floats2half2_rn(v.x, v.y);
    __half2 b = __floats2half2_rn(v.z, v.w);
    uint2 o; o.x = *(uint32_t*)&a; o.y = *(uint32_t*)&b;
    *(uint2*)(T0 + 4 * i) = o;
}

__global__ void wsplit(const float* __restrict__ W, __half* __restrict__ WT,
                       int Kd, int N, size_t sW, size_t sWT) {
    __shared__ float t[32][33];
    const int bz = blockIdx.z;
    W  += (size_t)bz * sW;
    WT += (size_t)bz * sWT;
    const int n0 = blockIdx.x * 32, k0 = blockIdx.y * 32;
    const int tx = threadIdx.x, ty = threadIdx.y;
    for (int i = 0; i < 32; i += 8)
        t[ty + i][tx] = W[(size_t)(k0 + ty + i) * N + n0 + tx];
    __syncthreads();
    for (int i = 0; i < 32; i += 8)
        WT[(size_t)(n0 + ty + i) * Kd + k0 + tx] = __float2half_rn(t[tx][ty + i]);
}

// ---------------------------------------------------------------------------
// Gram + normalize + score (Z fp16)
// ---------------------------------------------------------------------------
__device__ __forceinline__ void pair_of(int p, int& i, int& j) {
    int ii = 0, rem = p;
    while (rem >= NV - ii) { rem -= NV - ii; ii++; }
    i = ii; j = ii + rem;
}
#define CHUNK 256
#define MAXP_PER_WARP 10

__global__ void gram_score(const __half* __restrict__ Z, float* __restrict__ out) {
    __shared__ float chunk[NV][CHUNK];
    __shared__ float sG[NV * NV];
    const int b = blockIdx.x, tid = threadIdx.x;
    const int lane = tid & 31, warp = tid >> 5;

    int pi_i[MAXP_PER_WARP], pi_j[MAXP_PER_WARP];
    float accp[MAXP_PER_WARP];
#pragma unroll
    for (int pi = 0; pi < MAXP_PER_WARP; pi++) {
        int p = warp + pi * 8;
        if (p < NPAIR) pair_of(p, pi_i[pi], pi_j[pi]);
        else { pi_i[pi] = 0; pi_j[pi] = 0; }
        accp[pi] = 0.0f;
    }
    for (int h0 = 0; h0 < Hn; h0 += CHUNK) {
        __syncthreads();
        for (int i = tid; i < NV * (CHUNK / 8); i += 256) {
            int v = i / (CHUNK / 8);
            int h8 = (i % (CHUNK / 8)) * 8;
            uint4 val = *(const uint4*)(Z + (size_t)v * Bn * Hn + (size_t)b * Hn + h0 + h8);
            const __half2* hp = (const __half2*)&val;
#pragma unroll
            for (int q = 0; q < 4; q++) {
                float2 f = __half22float2(hp[q]);
                chunk[v][h8 + 2 * q]     = f.x;
                chunk[v][h8 + 2 * q + 1] = f.y;
            }
        }
        __syncthreads();
#pragma unroll
        for (int pi = 0; pi < MAXP_PER_WARP; pi++) {
            int p = warp + pi * 8;
            if (p < NPAIR) {
                const float* ri = chunk[pi_i[pi]];
                const float* rj = chunk[pi_j[pi]];
                float s = 0.0f;
#pragma unroll
                for (int t = 0; t < CHUNK / 32; t++)
                    s = fmaf(ri[lane + 32 * t], rj[lane + 32 * t], s);
                accp[pi] += s;
            }
        }
    }
#pragma unroll
    for (int pi = 0; pi < MAXP_PER_WARP; pi++) {
        int p = warp + pi * 8;
        if (p < NPAIR) {
            float s = accp[pi];
#pragma unroll
            for (int o = 16; o; o >>= 1) s += __shfl_xor_sync(0xffffffffu, s, o);
            if (lane == 0) {
                sG[pi_i[pi] * NV + pi_j[pi]] = s;
                sG[pi_j[pi] * NV + pi_i[pi]] = s;
            }
        }
    }
    __syncthreads();
    if (tid == 0) {
        float nm[NV];
#pragma unroll
        for (int i = 0; i < NV; i++) nm[i] = fmaxf(sqrtf(sG[i * NV + i]), EPSF);
        float total = 0.0f;
        for (int k = 1; k < NV; k++) {
            float pos = expf(sG[k] / (nm[0] * nm[k]));
            float neg = 0.0f;
            for (int l = 1; l < NV; l++)
                if (l != k) neg += expf(sG[k * NV + l] / (nm[k] * nm[l]));
            total += logf((pos + neg) / pos);
        }
        out[b] = total;
    }
}

// ---------------------------------------------------------------------------
// Launch
// ---------------------------------------------------------------------------
extern "C" void kernel_launch(void* const* d_in, const int* in_sizes, int n_in,
                              void* d_out, int out_size)
{
    const float* x   = (const float*)d_in[0];
    const float* Wt1 = (const float*)d_in[1];
    const float* bt1 = (const float*)d_in[2];
    const float* Wt2 = (const float*)d_in[3];
    const float* bt2 = (const float*)d_in[4];
    const float* We1 = (const float*)d_in[5];
    const float* be1 = (const float*)d_in[6];
    const float* We2 = (const float*)d_in[7];
    const float* be2 = (const float*)d_in[8];
    float* out = (float*)d_out;

    __half *T, *H, *Z, *WT1, *WT2, *WE1, *WE2;
    cudaGetSymbolAddress((void**)&T, g_T);
    cudaGetSymbolAddress((void**)&H, g_H);
    cudaGetSymbolAddress((void**)&Z, g_Z);
    cudaGetSymbolAddress((void**)&WT1, g_WT1);
    cudaGetSymbolAddress((void**)&WT2, g_WT2);
    cudaGetSymbolAddress((void**)&WE1, g_WE1);
    cudaGetSymbolAddress((void**)&WE2, g_WE2);

    xhalf<<<(Bn * Dn) / 1024, 256>>>(x, T);
    wsplit<<<dim3(Hn / 32, Dn / 32, KV), dim3(32, 8)>>>(
        Wt1, WT1, Dn, Hn, (size_t)Dn * Hn, (size_t)Hn * Dn);
    wsplit<<<dim3(Dn / 32, Hn / 32, KV), dim3(32, 8)>>>(
        Wt2, WT2, Hn, Dn, (size_t)Hn * Dn, (size_t)Dn * Hn);
    wsplit<<<dim3(Hn / 32, Dn / 32, 1), dim3(32, 8)>>>(We1, WE1, Dn, Hn, 0, 0);
    wsplit<<<dim3(Hn / 32, Hn / 32, 1), dim3(32, 8)>>>(We2, WE2, Hn, Hn, 0, 0);

    cudaFuncSetAttribute(gemm_mma<1>, cudaFuncAttributeMaxDynamicSharedMemorySize, GEMM_SMEM);
    cudaFuncSetAttribute(gemm_mma<0>, cudaFuncAttributeMaxDynamicSharedMemorySize, GEMM_SMEM);
    cudaFuncSetAttribute(gemm_mma<2>, cudaFuncAttributeMaxDynamicSharedMemorySize, GEMM_SMEM);

    // A1: H[k] = tanh(x @ Wt1[k] + bt1[k])
    gemm_mma<1><<<dim3(Hn / TILE_N, Bn / TILE_M, KV), 256, GEMM_SMEM>>>(
        T, WT1, bt1, H, Hn, Dn,
        (size_t)0, (size_t)Hn * Dn, (size_t)Hn, (size_t)Bn * Hn);

    // A2: T[1+k] = H[k] @ Wt2[k] + bt2[k]
    gemm_mma<0><<<dim3(Dn / TILE_N, Bn / TILE_M, KV), 256, GEMM_SMEM>>>(
        H, WT2, bt2, T + (size_t)Bn * Dn, Dn, Hn,
        (size_t)Bn * Hn, (size_t)Dn * Hn, (size_t)Dn, (size_t)Bn * Dn);

    // B1: H[v] = relu(T[v] @ We1 + be1)
    gemm_mma<2><<<dim3(Hn / TILE_N, Bn / TILE_M, NV), 256, GEMM_SMEM>>>(
        T, WE1, be1, H, Hn, Dn,
        (size_t)Bn * Dn, (size_t)0, (size_t)0, (size_t)Bn * Hn);

    // B2: Z[v] = H[v] @ We2 + be2  (fp16 out)
    gemm_mma<0><<<dim3(Hn / TILE_N, Bn / TILE_M, NV), 256, GEMM_SMEM>>>(
        H, WE2, be2, Z, Hn, Hn,
        (size_t)Bn * Hn, (size_t)0, (size_t)0, (size_t)Bn * Hn);

    gram_score<<<Bn, 256>>>(Z, out);
}

// round 13
// speedup vs baseline: 1.8002x; 1.1390x over previous
#include <cuda_runtime.h>
#include <cuda_fp16.h>
#include <cstddef>
#include <cstdint>

#define Bn 8192
#define Dn 512
#define Hn 1024
#define KV 11
#define NV 12
#define NPAIR 78
#define EPSF 1e-8f

// ---------------------------------------------------------------------------
// Scratch: fp16 activations [rows, K]; weights transposed fp16 WT[n, K];
// encodings Z in fp16.
// ---------------------------------------------------------------------------
__device__ __align__(1024) __half g_T[(size_t)NV * Bn * Dn];
__device__ __align__(1024) __half g_H[(size_t)NV * Bn * Hn];
__device__ __align__(1024) __half g_Z[(size_t)NV * Bn * Hn];
__device__ __align__(1024) __half g_WT1[(size_t)KV * Hn * Dn];
__device__ __align__(1024) __half g_WT2[(size_t)KV * Dn * Hn];
__device__ __align__(1024) __half g_WE1[(size_t)Hn * Dn];
__device__ __align__(1024) __half g_WE2[(size_t)Hn * Hn];

// ---------------------------------------------------------------------------
__device__ __forceinline__ uint32_t smem_u32(const void* p) {
    uint32_t a;
    asm("{ .reg .u64 t; cvta.to.shared.u64 t, %1; cvt.u32.u64 %0, t; }" : "=r"(a) : "l"(p));
    return a;
}
__device__ __forceinline__ void cpa16(uint32_t dst, const void* src) {
    asm volatile("cp.async.cg.shared.global [%0], [%1], 16;" :: "r"(dst), "l"(src) : "memory");
}
#define CP_COMMIT() asm volatile("cp.async.commit_group;" ::: "memory")
#define CP_WAIT0()  asm volatile("cp.async.wait_group 0;" ::: "memory")

__device__ __forceinline__ void ldm4(uint32_t* r, uint32_t addr) {
    asm volatile("ldmatrix.sync.aligned.m8n8.x4.shared.b16 {%0,%1,%2,%3}, [%4];"
                 : "=r"(r[0]), "=r"(r[1]), "=r"(r[2]), "=r"(r[3]) : "r"(addr));
}
// fp16 accumulate: d/c are 2 b32 regs (4 halves)
__device__ __forceinline__ void mma16816_f16(uint32_t* d, const uint32_t* a, const uint32_t* b) {
    asm volatile(
        "mma.sync.aligned.m16n8k16.row.col.f16.f16.f16.f16 "
        "{%0,%1}, {%2,%3,%4,%5}, {%6,%7}, {%0,%1};"
        : "+r"(d[0]), "+r"(d[1])
        : "r"(a[0]), "r"(a[1]), "r"(a[2]), "r"(a[3]), "r"(b[0]), "r"(b[1]));
}
__device__ __forceinline__ float tanh_fast(float x) {
    float y;
    asm("tanh.approx.f32 %0, %1;" : "=f"(y) : "f"(x));
    return y;
}

// ---------------------------------------------------------------------------
// fp16 GEMM (fp16 accum):  C = act(A @ Bw^T + bias),  A=[M,K], Bw=[N,K]
// CTA 128x256, K-chunk 64, 2 stages (96KB total) -> 2 CTAs/SM.
// 8 warps, 2m x 4n, warp tile 64x64.
// ---------------------------------------------------------------------------
#define TILE_M 128
#define TILE_N 256
#define BK 64
#define STAGES 2
#define A_BYTES (TILE_M * 128)
#define STAGE_BYTES (A_BYTES + TILE_N * 128)
#define GEMM_SMEM (STAGES * STAGE_BYTES)

template <int ACT>
__global__ void __launch_bounds__(256, 2) gemm_mma(
    const __half* __restrict__ A, const __half* __restrict__ Bw,
    const float* __restrict__ bias, __half* __restrict__ Cout,
    int N, int Kd, size_t sA, size_t sB, size_t sBias, size_t sC)
{
    extern __shared__ __align__(1024) char smem[];
    const uint32_t sb = smem_u32(smem);
    const int tid = threadIdx.x, wid = tid >> 5, lane = tid & 31;
    const int bz = blockIdx.z;
    A    += (size_t)bz * sA;
    Bw   += (size_t)bz * sB;
    bias += (size_t)bz * sBias;

    const int bm = blockIdx.y * TILE_M;
    const int bn = blockIdx.x * TILE_N;
    const int total = Kd / BK;

    // ---- producer mapping: 256 threads = 32 rows x 8 granules ----
    const int prow = tid >> 3;            // 0..31
    const int pch  = tid & 7;
    const uint32_t doff = (uint32_t)(prow * 128) +
                          (((uint32_t)(pch * 16)) ^ (uint32_t)((prow & 7) << 4));
    const __half* Ag = A  + (size_t)(bm + prow) * Kd + pch * 8;
    const __half* Bg = Bw + (size_t)(bn + prow) * Kd + pch * 8;

    // ---- warp compute mapping: 2 m-warps x 4 n-warps, warp tile 64x64 ----
    const int m_off = (wid & 1) * 64;
    const int n_off = (wid >> 1) * 64;
    const int ar = lane & 15, ah = lane >> 4;
    const uint32_t aXor = (uint32_t)((ar & 7) << 4);
    uint32_t aRow[4];
#pragma unroll
    for (int mi = 0; mi < 4; mi++)
        aRow[mi] = (uint32_t)((m_off + mi * 16 + ar) * 128);
    const uint32_t aKad = (uint32_t)(ah * 16);
    const int l8 = lane & 7, sel = lane >> 3;
    const uint32_t bXor = (uint32_t)((l8 & 7) << 4);
    uint32_t bRow[4];
#pragma unroll
    for (int j = 0; j < 4; j++)
        bRow[j] = (uint32_t)((n_off + j * 16 + ((sel >> 1) * 8) + l8) * 128);
    const uint32_t bKad = (uint32_t)((sel & 1) * 16);

    uint32_t acc[4][8][2];                // fp16x2 accumulators
#pragma unroll
    for (int mi = 0; mi < 4; mi++)
#pragma unroll
        for (int nj = 0; nj < 8; nj++) {
            acc[mi][nj][0] = 0u;
            acc[mi][nj][1] = 0u;
        }

    auto load_chunk = [&](int c, int s) {
        const int k0 = c * BK;
        const uint32_t ab = sb + s * STAGE_BYTES;
        const uint32_t bb = ab + A_BYTES;
#pragma unroll
        for (int i = 0; i < 4; i++)
            cpa16(ab + doff + (uint32_t)(i * 4096), Ag + (size_t)(32 * i) * Kd + k0);
#pragma unroll
        for (int i = 0; i < 8; i++)
            cpa16(bb + doff + (uint32_t)(i * 4096), Bg + (size_t)(32 * i) * Kd + k0);
    };

    // prologue: fill stage 0
    load_chunk(0, 0);
    CP_COMMIT();

    for (int it = 0; it < total; it++) {
        CP_WAIT0();                       // chunk `it` resident
        __syncthreads();                  // all warps done with the stage being overwritten
        const int nc = it + 1;
        if (nc < total) {
            load_chunk(nc, nc & 1);
            CP_COMMIT();
        }
        const uint32_t ab = sb + (it & 1) * STAGE_BYTES;
        const uint32_t bb = ab + A_BYTES;
#pragma unroll
        for (int ks = 0; ks < BK / 16; ks++) {
            uint32_t af[4][4];
            uint32_t bfr[8][2];
#pragma unroll
            for (int mi = 0; mi < 4; mi++)
                ldm4(af[mi], ab + aRow[mi] + (((uint32_t)(ks * 32) + aKad) ^ aXor));
#pragma unroll
            for (int j = 0; j < 4; j++) {
                uint32_t r[4];
                ldm4(r, bb + bRow[j] + (((uint32_t)(ks * 32) + bKad) ^ bXor));
                bfr[2 * j][0] = r[0]; bfr[2 * j][1] = r[1];
                bfr[2 * j + 1][0] = r[2]; bfr[2 * j + 1][1] = r[3];
            }
#pragma unroll
            for (int mi = 0; mi < 4; mi++)
#pragma unroll
                for (int nj = 0; nj < 8; nj++)
                    mma16816_f16(acc[mi][nj], af[mi], bfr[nj]);
        }
    }

    // ---- epilogue (fp16 out) ----
    const int crow = lane >> 2;
    const int ccol = (lane & 3) * 2;
#pragma unroll
    for (int nj = 0; nj < 8; nj++) {
        const int col = bn + n_off + nj * 8 + ccol;
        const float2 bb2 = *(const float2*)(bias + col);
#pragma unroll
        for (int mi = 0; mi < 4; mi++) {
            const int r0 = bm + m_off + mi * 16 + crow;
#pragma unroll
            for (int h = 0; h < 2; h++) {
                const int row = r0 + 8 * h;
                float2 f = __half22float2(*(const __half2*)&acc[mi][nj][h]);
                float v0 = f.x + bb2.x;
                float v1 = f.y + bb2.y;
                if (ACT == 1) { v0 = tanh_fast(v0); v1 = tanh_fast(v1); }
                else if (ACT == 2) { v0 = fmaxf(v0, 0.f); v1 = fmaxf(v1, 0.f); }
                __half2 hh = __halves2half2(__float2half_rn(v0), __float2half_rn(v1));
                __half* base = Cout + (size_t)bz * sC + (size_t)row * N + col;
                *(uint32_t*)base = *(uint32_t*)&hh;
            }
        }
    }
}

// ---------------------------------------------------------------------------
// Prep kernels
// ---------------------------------------------------------------------------
__global__ void xhalf(const float* __restrict__ x, __half* __restrict__ T0) {
    size_t i = (size_t)blockIdx.x * 256 + threadIdx.x;
    float4 v = *(const float4*)(x + 4 * i);
    __half2 a = __floats2half2_rn(v.x, v.y);
    __half2 b = __floats2half2_rn(v.z, v.w);
    uint2 o; o.x = *(uint32_t*)&a; o.y = *(uint32_t*)&b;
    *(uint2*)(T0 + 4 * i) = o;
}

__global__ void wsplit(const float* __restrict__ W, __half* __restrict__ WT,
                       int Kd, int N, size_t sW, size_t sWT) {
    __shared__ float t[32][33];
    const int bz = blockIdx.z;
    W  += (size_t)bz * sW;
    WT += (size_t)bz * sWT;
    const int n0 = blockIdx.x * 32, k0 = blockIdx.y * 32;
    const int tx = threadIdx.x, ty = threadIdx.y;
    for (int i = 0; i < 32; i += 8)
        t[ty + i][tx] = W[(size_t)(k0 + ty + i) * N + n0 + tx];
    __syncthreads();
    for (int i = 0; i < 32; i += 8)
        WT[(size_t)(n0 + ty + i) * Kd + k0 + tx] = __float2half_rn(t[tx][ty + i]);
}

// ---------------------------------------------------------------------------
// Gram + normalize + score (Z fp16)
// ---------------------------------------------------------------------------
__device__ __forceinline__ void pair_of(int p, int& i, int& j) {
    int ii = 0, rem = p;
    while (rem >= NV - ii) { rem -= NV - ii; ii++; }
    i = ii; j = ii + rem;
}
#define CHUNK 256
#define MAXP_PER_WARP 10

__global__ void gram_score(const __half* __restrict__ Z, float* __restrict__ out) {
    __shared__ float chunk[NV][CHUNK];
    __shared__ float sG[NV * NV];
    const int b = blockIdx.x, tid = threadIdx.x;
    const int lane = tid & 31, warp = tid >> 5;

    int pi_i[MAXP_PER_WARP], pi_j[MAXP_PER_WARP];
    float accp[MAXP_PER_WARP];
#pragma unroll
    for (int pi = 0; pi < MAXP_PER_WARP; pi++) {
        int p = warp + pi * 8;
        if (p < NPAIR) pair_of(p, pi_i[pi], pi_j[pi]);
        else { pi_i[pi] = 0; pi_j[pi] = 0; }
        accp[pi] = 0.0f;
    }
    for (int h0 = 0; h0 < Hn; h0 += CHUNK) {
        __syncthreads();
        for (int i = tid; i < NV * (CHUNK / 8); i += 256) {
            int v = i / (CHUNK / 8);
            int h8 = (i % (CHUNK / 8)) * 8;
            uint4 val = *(const uint4*)(Z + (size_t)v * Bn * Hn + (size_t)b * Hn + h0 + h8);
            const __half2* hp = (const __half2*)&val;
#pragma unroll
            for (int q = 0; q < 4; q++) {
                float2 f = __half22float2(hp[q]);
                chunk[v][h8 + 2 * q]     = f.x;
                chunk[v][h8 + 2 * q + 1] = f.y;
            }
        }
        __syncthreads();
#pragma unroll
        for (int pi = 0; pi < MAXP_PER_WARP; pi++) {
            int p = warp + pi * 8;
            if (p < NPAIR) {
                const float* ri = chunk[pi_i[pi]];
                const float* rj = chunk[pi_j[pi]];
                float s = 0.0f;
#pragma unroll
                for (int t = 0; t < CHUNK / 32; t++)
                    s = fmaf(ri[lane + 32 * t], rj[lane + 32 * t], s);
                accp[pi] += s;
            }
        }
    }
#pragma unroll
    for (int pi = 0; pi < MAXP_PER_WARP; pi++) {
        int p = warp + pi * 8;
        if (p < NPAIR) {
            float s = accp[pi];
#pragma unroll
            for (int o = 16; o; o >>= 1) s += __shfl_xor_sync(0xffffffffu, s, o);
            if (lane == 0) {
                sG[pi_i[pi] * NV + pi_j[pi]] = s;
                sG[pi_j[pi] * NV + pi_i[pi]] = s;
            }
        }
    }
    __syncthreads();
    if (tid == 0) {
        float nm[NV];
#pragma unroll
        for (int i = 0; i < NV; i++) nm[i] = fmaxf(sqrtf(sG[i * NV + i]), EPSF);
        float total = 0.0f;
        for (int k = 1; k < NV; k++) {
            float pos = expf(sG[k] / (nm[0] * nm[k]));
            float neg = 0.0f;
            for (int l = 1; l < NV; l++)
                if (l != k) neg += expf(sG[k * NV + l] / (nm[k] * nm[l]));
            total += logf((pos + neg) / pos);
        }
        out[b] = total;
    }
}

// ---------------------------------------------------------------------------
// Launch
// ---------------------------------------------------------------------------
extern "C" void kernel_launch(void* const* d_in, const int* in_sizes, int n_in,
                              void* d_out, int out_size)
{
    const float* x   = (const float*)d_in[0];
    const float* Wt1 = (const float*)d_in[1];
    const float* bt1 = (const float*)d_in[2];
    const float* Wt2 = (const float*)d_in[3];
    const float* bt2 = (const float*)d_in[4];
    const float* We1 = (const float*)d_in[5];
    const float* be1 = (const float*)d_in[6];
    const float* We2 = (const float*)d_in[7];
    const float* be2 = (const float*)d_in[8];
    float* out = (float*)d_out;

    __half *T, *H, *Z, *WT1, *WT2, *WE1, *WE2;
    cudaGetSymbolAddress((void**)&T, g_T);
    cudaGetSymbolAddress((void**)&H, g_H);
    cudaGetSymbolAddress((void**)&Z, g_Z);
    cudaGetSymbolAddress((void**)&WT1, g_WT1);
    cudaGetSymbolAddress((void**)&WT2, g_WT2);
    cudaGetSymbolAddress((void**)&WE1, g_WE1);
    cudaGetSymbolAddress((void**)&WE2, g_WE2);

    xhalf<<<(Bn * Dn) / 1024, 256>>>(x, T);
    wsplit<<<dim3(Hn / 32, Dn / 32, KV), dim3(32, 8)>>>(
        Wt1, WT1, Dn, Hn, (size_t)Dn * Hn, (size_t)Hn * Dn);
    wsplit<<<dim3(Dn / 32, Hn / 32, KV), dim3(32, 8)>>>(
        Wt2, WT2, Hn, Dn, (size_t)Hn * Dn, (size_t)Dn * Hn);
    wsplit<<<dim3(Hn / 32, Dn / 32, 1), dim3(32, 8)>>>(We1, WE1, Dn, Hn, 0, 0);
    wsplit<<<dim3(Hn / 32, Hn / 32, 1), dim3(32, 8)>>>(We2, WE2, Hn, Hn, 0, 0);

    cudaFuncSetAttribute(gemm_mma<1>, cudaFuncAttributeMaxDynamicSharedMemorySize, GEMM_SMEM);
    cudaFuncSetAttribute(gemm_mma<0>, cudaFuncAttributeMaxDynamicSharedMemorySize, GEMM_SMEM);
    cudaFuncSetAttribute(gemm_mma<2>, cudaFuncAttributeMaxDynamicSharedMemorySize, GEMM_SMEM);

    // A1: H[k] = tanh(x @ Wt1[k] + bt1[k])
    gemm_mma<1><<<dim3(Hn / TILE_N, Bn / TILE_M, KV), 256, GEMM_SMEM>>>(
        T, WT1, bt1, H, Hn, Dn,
        (size_t)0, (size_t)Hn * Dn, (size_t)Hn, (size_t)Bn * Hn);

    // A2: T[1+k] = H[k] @ Wt2[k] + bt2[k]
    gemm_mma<0><<<dim3(Dn / TILE_N, Bn / TILE_M, KV), 256, GEMM_SMEM>>>(
        H, WT2, bt2, T + (size_t)Bn * Dn, Dn, Hn,
        (size_t)Bn * Hn, (size_t)Dn * Hn, (size_t)Dn, (size_t)Bn * Dn);

    // B1: H[v] = relu(T[v] @ We1 + be1)
    gemm_mma<2><<<dim3(Hn / TILE_N, Bn / TILE_M, NV), 256, GEMM_SMEM>>>(
        T, WE1, be1, H, Hn, Dn,
        (size_t)Bn * Dn, (size_t)0, (size_t)0, (size_t)Bn * Hn);

    // B2: Z[v] = H[v] @ We2 + be2  (fp16 out)
    gemm_mma<0><<<dim3(Hn / TILE_N, Bn / TILE_M, NV), 256, GEMM_SMEM>>>(
        H, WE2, be2, Z, Hn, Hn,
        (size_t)Bn * Hn, (size_t)0, (size_t)0, (size_t)Bn * Hn);

    gram_score<<<Bn, 256>>>(Z, out);
}